// round 11
// baseline (speedup 1.0000x reference)
#include <cuda_runtime.h>
#include <cstdint>

// WeightedFeatureInteraction: out[b] = sum_{i<j} w[i,j] * <x[b,i,:], x[b,j,:]>
//   inputs [B, 64*128] fp32, field_weights [64,64] fp32, out [B,1] fp32.
//
// Round 10: R8 (warp-pair per batch row, 16 warps/SM) with the producer/
// consumer race fixed: cp.async issue of chunk m+2 moved AFTER the pair
// barrier (wait_group 1 before it). Barrier now orders partner's compute of
// chunk m-1 before its buffer (m+2)%3 is overwritten.

#define NF 64
#define ND 128
#define THREADS 512
#define PAIRS 8                        // pairs per CTA
#define NTILES 20
#define TPW 10                         // tiles per warp
#define WBYTES (NTILES * 128 * 4)      // 10240: masked W fragments
#define CHUNK_BYTES 8192               // 64 rows x 32 cols fp32
#define SMEM_RED (WBYTES)              // float red[8]
#define SMEM_STAGE (WBYTES + 64)
#define SMEM_TOTAL (SMEM_STAGE + PAIRS * 3 * CHUNK_BYTES)

__device__ static const int TI[NTILES] = {0,0,0,0,0,0,0,0, 1,1,1,1,1,1, 2,2,2,2, 3,3};
__device__ static const int TJ[NTILES] = {0,1,2,3,4,5,6,7, 2,3,4,5,6,7, 4,5,6,7, 6,7};

__device__ __forceinline__ uint32_t cvt_tf32(uint32_t fbits) {
    uint32_t r;
    asm("cvt.rna.tf32.f32 %0, %1;" : "=r"(r) : "f"(__uint_as_float(fbits)));
    return r;
}

__device__ __forceinline__ void mma_tf32(float* d,
                                         uint32_t a0, uint32_t a1, uint32_t a2, uint32_t a3,
                                         uint32_t b0, uint32_t b1) {
    asm volatile("mma.sync.aligned.m16n8k8.row.col.f32.tf32.tf32.f32 "
                 "{%0,%1,%2,%3}, {%4,%5,%6,%7}, {%8,%9}, {%0,%1,%2,%3};"
                 : "+f"(d[0]), "+f"(d[1]), "+f"(d[2]), "+f"(d[3])
                 : "r"(a0), "r"(a1), "r"(a2), "r"(a3), "r"(b0), "r"(b1));
}

__device__ __forceinline__ uint32_t smem_u32(const void* p) {
    uint32_t a;
    asm("{ .reg .u64 t; cvta.to.shared.u64 t, %1; cvt.u32.u64 %0, t; }"
        : "=r"(a) : "l"(p));
    return a;
}

// Each warp of the pair copies HALF of a 64x32 chunk (8 cp.async.cg of 16B
// per lane). h selects the row half-set. Always commits a group.
__device__ __forceinline__ void issue_chunk(const float* __restrict__ x,
                                            int b_m, int B, int c,
                                            uint32_t dst_base, int lane, int h) {
    if (b_m < B) {
        const int wrow = (h << 2) + (lane >> 3);          // 0..7
        const int wcol = (lane & 7) * 4;
        const float* src = x + (size_t)b_m * (NF * ND) + c * 32 + wcol;
#pragma unroll
        for (int u = 0; u < 8; ++u) {
            const int row = 8 * u + wrow;
            const uint32_t dst =
                dst_base + (uint32_t)(row * 32 + (wcol ^ ((row & 7) << 2))) * 4;
            const float* s = src + (size_t)row * ND;
            asm volatile("cp.async.cg.shared.global [%0], [%1], 16;"
                         :: "r"(dst), "l"(s) : "memory");
        }
    }
    asm volatile("cp.async.commit_group;" ::: "memory");
}

extern "C" __global__ void __launch_bounds__(THREADS, 1)
wfi_mma(const float* __restrict__ x, const float* __restrict__ fw,
        float* __restrict__ out, int B, int PS) {
    extern __shared__ char smem[];
    const int tid = threadIdx.x, wq = tid >> 5, lane = tid & 31;
    const int pair = wq >> 1, h = wq & 1;
    float* wsm = (float*)smem;
    float* red = (float*)(smem + SMEM_RED);

    // Masked W fragments in mma C-fragment layout.
    for (int idx = tid; idx < NTILES * 128; idx += THREADS) {
        int t = idx >> 7, rem = idx & 127, lp = rem >> 2, r = rem & 3;
        int i = TI[t] * 16 + (lp >> 2) + (r >> 1) * 8;
        int j = TJ[t] * 8 + (lp & 3) * 2 + (r & 1);
        wsm[idx] = (j > i) ? fw[i * NF + j] : 0.0f;
    }
    __syncthreads();

    const int b0 = blockIdx.x * PAIRS + pair;
    if (b0 >= B) return;

    uint32_t bufa[3];
    const uint32_t* bufw[3];
#pragma unroll
    for (int r = 0; r < 3; ++r) {
        int off = SMEM_STAGE + (pair * 3 + r) * CHUNK_BYTES;
        bufa[r] = smem_u32(smem) + (uint32_t)off;
        bufw[r] = (const uint32_t*)(smem + off);
    }

    const int g  = lane >> 2;
    const int tg = lane & 3;
    const int bar_id = pair + 1;

    // Prologue: chunks 0 and 1 of b0 in flight.
    issue_chunk(x, b0, B, 0, bufa[0], lane, h);
    issue_chunk(x, b0, B, 1, bufa[1], lane, h);

    int m = 0;
    for (int b = b0; b < B; b += PS) {
        float acc[TPW][4];
#pragma unroll
        for (int t = 0; t < TPW; ++t)
#pragma unroll
            for (int r = 0; r < 4; ++r) acc[t][r] = 0.0f;

#pragma unroll 1
        for (int c = 0; c < 4; ++c, ++m) {
            // Chunk m complete (my half); barrier orders BOTH halves of m
            // visible AND both warps done computing chunk m-1.
            asm volatile("cp.async.wait_group 1;" ::: "memory");
            asm volatile("bar.sync %0, %1;" :: "r"(bar_id), "r"(64) : "memory");

            // Now safe to overwrite buffer (m+2)%3 == (m-1)%3.
            const int m2 = m + 2;
            issue_chunk(x, b0 + (m2 >> 2) * PS, B, m2 & 3, bufa[m2 % 3], lane, h);

            const uint32_t* buf = bufw[m % 3];
#pragma unroll
            for (int s = 0; s < 4; ++s) {
                uint32_t fx[8], fy[8];
#pragma unroll
                for (int r = 0; r < 8; ++r) {
                    const uint32_t base = (8 * r + g) * 32;
                    fx[r] = cvt_tf32(buf[base + ((8 * s + tg)     ^ (g << 2))]);
                    fy[r] = cvt_tf32(buf[base + ((8 * s + tg + 4) ^ (g << 2))]);
                }
#pragma unroll
                for (int tt = 0; tt < TPW; ++tt) {
                    const int t = h * TPW + tt;
                    const int ti = TI[t], tj = TJ[t];
                    mma_tf32(acc[tt], fx[2 * ti], fx[2 * ti + 1],
                             fy[2 * ti], fy[2 * ti + 1], fx[tj], fy[tj]);
                }
            }
        }

        // Epilogue: weighted reduce of this warp's tiles, combine across pair.
        float s = 0.0f;
#pragma unroll
        for (int tt = 0; tt < TPW; ++tt) {
            const int t = h * TPW + tt;
            float4 w4 = *(const float4*)(wsm + (t * 32 + lane) * 4);
            s = fmaf(w4.x, acc[tt][0], s);
            s = fmaf(w4.y, acc[tt][1], s);
            s = fmaf(w4.z, acc[tt][2], s);
            s = fmaf(w4.w, acc[tt][3], s);
        }
#pragma unroll
        for (int off = 16; off > 0; off >>= 1)
            s += __shfl_xor_sync(0xFFFFFFFFu, s, off);

        if (h == 1 && lane == 0) red[pair] = s;
        asm volatile("bar.sync %0, %1;" :: "r"(bar_id), "r"(64) : "memory");
        if (h == 0 && lane == 0) out[b] = s + red[pair];
    }
}

extern "C" void kernel_launch(void* const* d_in, const int* in_sizes, int n_in,
                              void* d_out, int out_size) {
    const float* x  = (const float*)d_in[0];
    const float* fw = (const float*)d_in[1];
    float* out      = (float*)d_out;

    int B = in_sizes[0] / (NF * ND);

    int dev = 0, nsm = 148;
    cudaGetDevice(&dev);
    cudaDeviceGetAttribute(&nsm, cudaDevAttrMultiProcessorCount, dev);

    cudaFuncSetAttribute(wfi_mma, cudaFuncAttributeMaxDynamicSharedMemorySize, SMEM_TOTAL);

    int grid = nsm;
    int PS = grid * PAIRS;             // batch stride per outer iteration
    wfi_mma<<<grid, THREADS, SMEM_TOTAL>>>(x, fw, out, B, PS);
}

// round 14
// speedup vs baseline: 4.1896x; 4.1896x over previous
#include <cuda_runtime.h>
#include <cstdint>

// WeightedFeatureInteraction: out[b] = sum_{i<j} w[i,j] * <x[b,i,:], x[b,j,:]>
//   inputs [B, 64*128] fp32, field_weights [64,64] fp32, out [B,1] fp32.
//
// Round 11: R7 structure (one warp per batch row, private triple-buffered
// cp.async staging, tf32 mma.sync Gram) scaled to 12 warps/SM as
// 2 CTAs x 6 warps with 4KB chunks (64 rows x 16 cols). Register-safe
// (<=170 regs @ 384 thr/SM), smem-safe (82KB/CTA). No cross-warp sharing.

#define NF 64
#define ND 128
#define THREADS 192
#define WPC 6
#define NTILES 20
#define WBYTES (NTILES * 128 * 4)         // 10240: masked W fragments
#define CH_COLS 16
#define CHUNK_BYTES 4096                  // 64 rows x 16 cols fp32
#define NCHUNK 8                          // chunks per batch row (K=128)
#define SMEM_TOTAL (WBYTES + WPC * 3 * CHUNK_BYTES)   // 10240 + 73728 = 83968

__device__ static const int TI[NTILES] = {0,0,0,0,0,0,0,0, 1,1,1,1,1,1, 2,2,2,2, 3,3};
__device__ static const int TJ[NTILES] = {0,1,2,3,4,5,6,7, 2,3,4,5,6,7, 4,5,6,7, 6,7};

__device__ __forceinline__ uint32_t cvt_tf32(uint32_t fbits) {
    uint32_t r;
    asm("cvt.rna.tf32.f32 %0, %1;" : "=r"(r) : "f"(__uint_as_float(fbits)));
    return r;
}

__device__ __forceinline__ void mma_tf32(float* d,
                                         uint32_t a0, uint32_t a1, uint32_t a2, uint32_t a3,
                                         uint32_t b0, uint32_t b1) {
    asm volatile("mma.sync.aligned.m16n8k8.row.col.f32.tf32.tf32.f32 "
                 "{%0,%1,%2,%3}, {%4,%5,%6,%7}, {%8,%9}, {%0,%1,%2,%3};"
                 : "+f"(d[0]), "+f"(d[1]), "+f"(d[2]), "+f"(d[3])
                 : "r"(a0), "r"(a1), "r"(a2), "r"(a3), "r"(b0), "r"(b1));
}

__device__ __forceinline__ uint32_t smem_u32(const void* p) {
    uint32_t a;
    asm("{ .reg .u64 t; cvta.to.shared.u64 t, %1; cvt.u32.u64 %0, t; }"
        : "=r"(a) : "l"(p));
    return a;
}

// Issue one 64x16 chunk: 8 cp.async.cg of 16B per lane into the swizzled
// buffer (col' = col ^ ((row&6)<<1)). Always commits a group.
__device__ __forceinline__ void issue_chunk(const float* __restrict__ x,
                                            int b_m, int B, int c,
                                            uint32_t dst_base, int lane) {
    if (b_m < B) {
        const int row0   = lane >> 2;            // 0..7
        const int colblk = (lane & 3) * 4;       // 0,4,8,12
        const float* src = x + (size_t)b_m * (NF * ND) + c * CH_COLS + colblk;
#pragma unroll
        for (int u = 0; u < 8; ++u) {
            const int row = 8 * u + row0;
            const uint32_t woff =
                (uint32_t)(row * CH_COLS + (colblk ^ ((row & 6) << 1)));
            const float* s = src + (size_t)row * ND;
            asm volatile("cp.async.cg.shared.global [%0], [%1], 16;"
                         :: "r"(dst_base + woff * 4), "l"(s) : "memory");
        }
    }
    asm volatile("cp.async.commit_group;" ::: "memory");
}

extern "C" __global__ void __launch_bounds__(THREADS, 2)
wfi_mma(const float* __restrict__ x, const float* __restrict__ fw,
        float* __restrict__ out, int B, int nwarps) {
    extern __shared__ char smem[];
    const int tid = threadIdx.x, wq = tid >> 5, lane = tid & 31;
    float* wsm = (float*)smem;

    // Masked W fragments in mma C-fragment layout.
    for (int idx = tid; idx < NTILES * 128; idx += THREADS) {
        int t = idx >> 7, rem = idx & 127, lp = rem >> 2, r = rem & 3;
        int i = TI[t] * 16 + (lp >> 2) + (r >> 1) * 8;
        int j = TJ[t] * 8 + (lp & 3) * 2 + (r & 1);
        wsm[idx] = (j > i) ? fw[i * NF + j] : 0.0f;
    }
    __syncthreads();

    const int b0 = blockIdx.x * WPC + wq;
    if (b0 >= B) return;

    uint32_t bufa[3];
    const uint32_t* bufw[3];
#pragma unroll
    for (int r = 0; r < 3; ++r) {
        int off = WBYTES + (wq * 3 + r) * CHUNK_BYTES;
        bufa[r] = smem_u32(smem) + (uint32_t)off;
        bufw[r] = (const uint32_t*)(smem + off);
    }

    const int g  = lane >> 2;
    const int tg = lane & 3;
    const int gsw = (g & 6) << 1;     // column swizzle for fragment reads

    // Prologue: chunks 0, 1 of b0 in flight.
    issue_chunk(x, b0, B, 0, bufa[0], lane);
    issue_chunk(x, b0, B, 1, bufa[1], lane);

    int m = 0;
    for (int b = b0; b < B; b += nwarps) {
        float acc[NTILES][4];
#pragma unroll
        for (int t = 0; t < NTILES; ++t)
#pragma unroll
            for (int r = 0; r < 4; ++r) acc[t][r] = 0.0f;

#pragma unroll 1
        for (int c = 0; c < NCHUNK; ++c, ++m) {
            const int m2 = m + 2;
            // Safe: this warp finished chunk m-1 (== buffer m2%3) last iter.
            issue_chunk(x, b0 + (m2 >> 3) * nwarps, B, m2 & 7,
                        bufa[m2 % 3], lane);
            asm volatile("cp.async.wait_group 2;" ::: "memory");
            __syncwarp();

            const uint32_t* buf = bufw[m % 3];
#pragma unroll
            for (int s = 0; s < 2; ++s) {
                uint32_t fx[8], fy[8];
#pragma unroll
                for (int r = 0; r < 8; ++r) {
                    const uint32_t base = (8 * r + g) * CH_COLS;
                    fx[r] = cvt_tf32(buf[base + ((8 * s + tg)     ^ gsw)]);
                    fy[r] = cvt_tf32(buf[base + ((8 * s + tg + 4) ^ gsw)]);
                }
#pragma unroll
                for (int t = 0; t < NTILES; ++t) {
                    const int ti = TI[t], tj = TJ[t];
                    mma_tf32(acc[t], fx[2 * ti], fx[2 * ti + 1],
                             fy[2 * ti], fy[2 * ti + 1], fx[tj], fy[tj]);
                }
            }
        }

        // Epilogue: weighted reduce of Gram fragments.
        float s = 0.0f;
#pragma unroll
        for (int t = 0; t < NTILES; ++t) {
            float4 w4 = *(const float4*)(wsm + (t * 32 + lane) * 4);
            s = fmaf(w4.x, acc[t][0], s);
            s = fmaf(w4.y, acc[t][1], s);
            s = fmaf(w4.z, acc[t][2], s);
            s = fmaf(w4.w, acc[t][3], s);
        }
#pragma unroll
        for (int off = 16; off > 0; off >>= 1)
            s += __shfl_xor_sync(0xFFFFFFFFu, s, off);
        if (lane == 0) out[b] = s;
    }
}

extern "C" void kernel_launch(void* const* d_in, const int* in_sizes, int n_in,
                              void* d_out, int out_size) {
    const float* x  = (const float*)d_in[0];
    const float* fw = (const float*)d_in[1];
    float* out      = (float*)d_out;

    int B = in_sizes[0] / (NF * ND);

    int dev = 0, nsm = 148;
    cudaGetDevice(&dev);
    cudaDeviceGetAttribute(&nsm, cudaDevAttrMultiProcessorCount, dev);

    cudaFuncSetAttribute(wfi_mma, cudaFuncAttributeMaxDynamicSharedMemorySize, SMEM_TOTAL);

    int grid = 2 * nsm;                 // 2 CTAs per SM
    int nwarps = grid * WPC;
    wfi_mma<<<grid, THREADS, SMEM_TOTAL>>>(x, fw, out, B, nwarps);
}